// round 11
// baseline (speedup 1.0000x reference)
#include <cuda_runtime.h>

// RayTracing, SINGLE fused kernel, block-local compaction:
//  Phase 1: trace 256 rays/block (1 thread/ray), write all outputs, push
//           unfinished (smask) rays into a shared-memory queue.
//  Phase 2: sqrt-free 100-step scan at 4 threads/ray (25 steps/lane; one pass
//           covers 64 rays, enough for the typical ~44-entry block queue).
//           Quad shuffle reduction, exact first-occurrence tie-break.
//           Non-sec rays finalize with z_o; sec rays push bracket to queue2.
//  Phase 3: secant at 1 thread/ray over queue2.
//  __launch_bounds__(256, 6) forces <=42 regs -> 6 blocks/SM (48 warps).
//
// Output layout (float32): [curr_pts (N*3)][net_mask (N)][acc_s (N)], N = out_size/5.
// object_mask arrives as int32.

namespace rt {

constexpr int   ST_ITERS   = 10;
constexpr float SDF_THRESH = 5e-5f;
constexpr int   NSTEPS     = 100;
constexpr int   NSECANT    = 8;
constexpr float INV99      = 1.0f / 99.0f;
constexpr float R2THRESH   = 0.25f;    // SDF_RADIUS^2
constexpr int   LPR        = 4;        // lanes per ray in scan
constexpr int   KPL        = 25;       // 100/4, exact
constexpr int   BLK        = 256;

__device__ __forceinline__ float fsqrt_fast(float x) {
    float y;
    asm("sqrt.approx.f32 %0, %1;" : "=f"(y) : "f"(x));
    return y;
}

// sdf(p) = sqrt(|p|^2 + 1e-12) - 0.5
__device__ __forceinline__ float sdf_p(float px, float py, float pz) {
    float q = fmaf(px, px, fmaf(py, py, fmaf(pz, pz, 1e-12f)));
    return fsqrt_fast(q) - 0.5f;
}

__device__ __forceinline__ float sdf_at(float ox, float oy, float oz,
                                        float dx, float dy, float dz, float t) {
    return sdf_p(fmaf(t, dx, ox), fmaf(t, dy, oy), fmaf(t, dz, oz));
}

// |o + t*d|^2 + 1e-12 (no sqrt)
__device__ __forceinline__ float q_at(float ox, float oy, float oz,
                                      float dx, float dy, float dz, float t) {
    float px = fmaf(t, dx, ox);
    float py = fmaf(t, dy, oy);
    float pz = fmaf(t, dz, oz);
    return fmaf(px, px, fmaf(py, py, fmaf(pz, pz, 1e-12f)));
}

__global__ void __launch_bounds__(BLK, 6)
fused_kernel(const float* __restrict__ cam,
             const float* __restrict__ dirs,
             const int* __restrict__ objm,
             float* __restrict__ out, int n)
{
    const unsigned FULL = 0xffffffffu;
    __shared__ int   s_cnt, s2_cnt;
    __shared__ int   s_rid[BLK];
    __shared__ float s_lo[BLK], s_hi[BLK];
    __shared__ int   s2_rid[BLK];
    __shared__ float s2_zl[BLK], s2_zh[BLK];

    int tid = threadIdx.x;
    if (tid == 0) { s_cnt = 0; s2_cnt = 0; }
    __syncthreads();

    // ================= Phase 1: trace =================
    int i = blockIdx.x * BLK + tid;
    bool valid = i < n;
    int j = valid ? i : 0;

    float ox = cam[3 * j + 0], oy = cam[3 * j + 1], oz = cam[3 * j + 2];
    float dx = dirs[3 * j + 0], dy = dirs[3 * j + 1], dz = dirs[3 * j + 2];

    // sphere intersect with bounding sphere R=1
    float a = fmaf(dx, dx, fmaf(dy, dy, dz * dz));
    float b = 2.0f * fmaf(ox, dx, fmaf(oy, dy, oz * dz));
    float c = fmaf(ox, ox, fmaf(oy, oy, oz * oz)) - 1.0f;
    float under = fmaf(b, b, -4.0f * a * c);
    bool  mask = under > 0.0f;
    float sq = fsqrt_fast(fmaxf(under, 0.0f));
    float nearv = mask ? (-sq - b) * 0.5f : 0.0f;
    float farv  = mask ? ( sq - b) * 0.5f : 0.0f;
    nearv = fmaxf(nearv, 0.01f);
    farv  = fmaxf(farv, 0.01f);

    // bidirectional sphere tracing
    bool us = mask, ue = mask;
    float accs = nearv, acce = farv;
    float csx = mask ? fmaf(nearv, dx, ox) : 0.0f;
    float csy = mask ? fmaf(nearv, dy, oy) : 0.0f;
    float csz = mask ? fmaf(nearv, dz, oz) : 0.0f;
    float cex = mask ? fmaf(farv, dx, ox) : 0.0f;
    float cey = mask ? fmaf(farv, dy, oy) : 0.0f;
    float cez = mask ? fmaf(farv, dz, oz) : 0.0f;
    float ns = us ? sdf_p(csx, csy, csz) : 0.0f;
    float ne = ue ? sdf_p(cex, cey, cez) : 0.0f;

#pragma unroll
    for (int it = 0; it < ST_ITERS; ++it) {
        float cs = us ? ns : 0.0f;
        cs = (cs <= SDF_THRESH) ? 0.0f : cs;
        us = us && (cs > SDF_THRESH);
        float ce = ue ? ne : 0.0f;
        ce = (ce <= SDF_THRESH) ? 0.0f : ce;
        ue = ue && (ce > SDF_THRESH);

        accs += cs;
        acce -= ce;
        csx = fmaf(accs, dx, ox); csy = fmaf(accs, dy, oy); csz = fmaf(accs, dz, oz);
        cex = fmaf(acce, dx, ox); cey = fmaf(acce, dy, oy); cez = fmaf(acce, dz, oz);
        ns = us ? sdf_p(csx, csy, csz) : 0.0f;
        ne = ue ? sdf_p(cex, cey, cez) : 0.0f;

        // line search: LINE_STEP_ITERS = 1, step = 0.5
        bool nps = ns < 0.0f;
        bool npe = ne < 0.0f;
        {
            float accs2 = fmaf(-0.5f, cs, accs);
            float x = fmaf(accs2, dx, ox), y = fmaf(accs2, dy, oy), z = fmaf(accs2, dz, oz);
            float s2 = sdf_p(x, y, z);
            if (nps) { accs = accs2; csx = x; csy = y; csz = z; ns = s2; }
        }
        {
            float acce2 = fmaf(0.5f, ce, acce);
            float x = fmaf(acce2, dx, ox), y = fmaf(acce2, dy, oy), z = fmaf(acce2, dz, oz);
            float s2 = sdf_p(x, y, z);
            if (npe) { acce = acce2; cex = x; cey = y; cez = z; ne = s2; }
        }
        bool ok = accs < acce;
        us = us && ok;
        ue = ue && ok;
    }
    // final _upd_mask on start side
    {
        float cs = us ? ns : 0.0f;
        cs = (cs <= SDF_THRESH) ? 0.0f : cs;
        us = us && (cs > SDF_THRESH);
    }

    bool netm  = accs < acce;
    bool smask = us && valid;

    if (valid) {
        out[3 * i + 0] = csx;
        out[3 * i + 1] = csy;
        out[3 * i + 2] = csz;
        out[3 * n + i] = netm ? 1.0f : 0.0f;
        out[4 * n + i] = accs;
    }

    // block-local compaction of smask rays
    if (smask) {
        int q = atomicAdd(&s_cnt, 1);
        s_rid[q] = i;
        s_lo[q]  = accs;
        s_hi[q]  = acce;
    }
    __syncthreads();

    // ================= Phase 2: scan (4 threads/ray) =================
    int cnt = s_cnt;
    int sub = tid & (LPR - 1);          // lane in quad

    for (int base = 0; base < cnt; base += BLK / LPR) {
        int rslot = base + (tid >> 2);
        bool active = rslot < cnt;
        int q = active ? rslot : 0;

        int rid = s_rid[q];
        float smin = s_lo[q];
        float smax = s_hi[q];
        float range = smax - smin;

        float rox = cam[3 * rid + 0], roy = cam[3 * rid + 1], roz = cam[3 * rid + 2];
        float rdx = dirs[3 * rid + 0], rdy = dirs[3 * rid + 1], rdz = dirs[3 * rid + 2];
        bool obj = objm[rid] != 0;

        int   kbase = sub * KPL;
        int   ind_neg = NSTEPS, oidx = NSTEPS - 1;
        float best_q = 1e30f;
#pragma unroll 5
        for (int kk = 0; kk < KPL; ++kk) {
            int k = kbase + kk;
            float t  = (float)k * INV99;
            float z  = fmaf(t, range, smin);
            float qv = q_at(rox, roy, roz, rdx, rdy, rdz, z);
            ind_neg  = min(ind_neg, (qv < R2THRESH) ? k : NSTEPS);
            if (qv < best_q) { best_q = qv; oidx = k; }
        }

        // quad reduction (xor 1,2 stays inside the quad)
#pragma unroll
        for (int m = 1; m < LPR; m <<= 1) {
            int   in2 = __shfl_xor_sync(FULL, ind_neg, m);
            float bq2 = __shfl_xor_sync(FULL, best_q, m);
            int   oi2 = __shfl_xor_sync(FULL, oidx, m);
            ind_neg = min(ind_neg, in2);
            if (bq2 < best_q || (bq2 == best_q && oi2 < oidx)) {
                best_q = bq2; oidx = oi2;
            }
        }

        bool net_surface = (ind_neg < NSTEPS);
        int  ind = net_surface ? ind_neg : (NSTEPS - 1);
        bool sec = net_surface && obj;   // complement of p_out over queued rays

        if (active && sub == 0) {
            out[3 * n + rid] = net_surface ? 1.0f : 0.0f;
            if (!sec) {
                float z_o = fmaf((float)oidx * INV99, range, smin);
                out[3 * rid + 0] = fmaf(z_o, rdx, rox);
                out[3 * rid + 1] = fmaf(z_o, rdy, roy);
                out[3 * rid + 2] = fmaf(z_o, rdz, roz);
                out[4 * n + rid] = z_o;
            } else {
                int   ilow  = (ind > 0) ? (ind - 1) : 0;
                float z_ind = fmaf((float)ind * INV99, range, smin);
                float z_l   = fmaf((float)ilow * INV99, range, smin);
                int q2 = atomicAdd(&s2_cnt, 1);
                s2_rid[q2] = rid;
                s2_zl[q2]  = z_l;
                s2_zh[q2]  = z_ind;
            }
        }
    }
    __syncthreads();

    // ================= Phase 3: secant (1 thread/ray) =================
    int cnt2 = s2_cnt;
    for (int q = tid; q < cnt2; q += BLK) {
        int   rid = s2_rid[q];
        float zl  = s2_zl[q];
        float zh  = s2_zh[q];

        float rox = cam[3 * rid + 0], roy = cam[3 * rid + 1], roz = cam[3 * rid + 2];
        float rdx = dirs[3 * rid + 0], rdy = dirs[3 * rid + 1], rdz = dirs[3 * rid + 2];

        float sl = sdf_at(rox, roy, roz, rdx, rdy, rdz, zl);
        float sh = sdf_at(rox, roy, roz, rdx, rdy, rdz, zh);

        float den = sh - sl;
        den = (den == 0.0f) ? 1.0f : den;
        float z = zl - sl * __fdividef(zh - zl, den);
#pragma unroll
        for (int k = 0; k < NSECANT; ++k) {
            float s = sdf_at(rox, roy, roz, rdx, rdy, rdz, z);
            if (s > 0.0f) { zl = z; sl = s; }
            if (s < 0.0f) { zh = z; sh = s; }
            den = sh - sl;
            den = (den == 0.0f) ? 1.0f : den;
            z = zl - sl * __fdividef(zh - zl, den);
        }

        out[3 * rid + 0] = fmaf(z, rdx, rox);
        out[3 * rid + 1] = fmaf(z, rdy, roy);
        out[3 * rid + 2] = fmaf(z, rdz, roz);
        out[4 * n + rid] = z;
        // net_mask for sec rays already written in phase 2
    }
}

} // namespace rt

extern "C" void kernel_launch(void* const* d_in, const int* in_sizes, int n_in,
                              void* d_out, int out_size)
{
    const float* cam  = (const float*)d_in[0];
    const float* dirs = (const float*)d_in[1];
    const int*   objm = (const int*)d_in[2];
    float* out = (float*)d_out;

    int n = out_size / 5;
    int blocks = (n + rt::BLK - 1) / rt::BLK;
    rt::fused_kernel<<<blocks, rt::BLK>>>(cam, dirs, objm, out, n);
}

// round 12
// speedup vs baseline: 1.2909x; 1.2909x over previous
#include <cuda_runtime.h>

// RayTracing, SINGLE fused kernel, block-local compaction, QUADRATIC sdf:
//  along a ray, |o+t*d|^2 = a*t^2 + b*t + |o|^2, so every sdf eval is
//  2 FMA (+ sqrt where the value is needed) instead of 6 FMA.
//  Phase 1: trace 256 rays/block (1 thread/ray) -> outputs + smask queue.
//  Phase 2: sqrt-free 100-step scan at 4 threads/ray (quad shuffle reduce,
//           exact first-occurrence tie-break). Non-sec rays finalize with z_o;
//           sec rays push bracket to queue2.
//  Phase 3: secant at 1 thread/ray over queue2.
//
// Output layout (float32): [curr_pts (N*3)][net_mask (N)][acc_s (N)], N = out_size/5.
// object_mask arrives as int32.

namespace rt {

constexpr int   ST_ITERS   = 10;
constexpr float SDF_THRESH = 5e-5f;
constexpr int   NSTEPS     = 100;
constexpr int   NSECANT    = 8;
constexpr float INV99      = 1.0f / 99.0f;
constexpr float R2THRESH   = 0.25f;    // SDF_RADIUS^2
constexpr int   LPR        = 4;        // lanes per ray in scan
constexpr int   KPL        = 25;       // 100/4, exact
constexpr int   BLK        = 256;

__device__ __forceinline__ float fsqrt_fast(float x) {
    float y;
    asm("sqrt.approx.f32 %0, %1;" : "=f"(y) : "f"(x));
    return y;
}

// q(t) = a*t^2 + b*t + qc  (qc = |o|^2 + 1e-12)
__device__ __forceinline__ float q_quad(float qa, float qb, float qc, float t) {
    return fmaf(t, fmaf(t, qa, qb), qc);
}

// sdf along ray = sqrt(q(t)) - 0.5
__device__ __forceinline__ float s_quad(float qa, float qb, float qc, float t) {
    return fsqrt_fast(q_quad(qa, qb, qc, t)) - 0.5f;
}

__global__ void __launch_bounds__(BLK, 6)
fused_kernel(const float* __restrict__ cam,
             const float* __restrict__ dirs,
             const int* __restrict__ objm,
             float* __restrict__ out, int n)
{
    const unsigned FULL = 0xffffffffu;
    __shared__ int   s_cnt, s2_cnt;
    __shared__ int   s_rid[BLK];
    __shared__ float s_lo[BLK], s_hi[BLK];
    __shared__ int   s2_rid[BLK];
    __shared__ float s2_zl[BLK], s2_zh[BLK];

    int tid = threadIdx.x;
    if (tid == 0) { s_cnt = 0; s2_cnt = 0; }
    __syncthreads();

    // ================= Phase 1: trace =================
    int i = blockIdx.x * BLK + tid;
    bool valid = i < n;
    int j = valid ? i : 0;

    float ox = cam[3 * j + 0], oy = cam[3 * j + 1], oz = cam[3 * j + 2];
    float dx = dirs[3 * j + 0], dy = dirs[3 * j + 1], dz = dirs[3 * j + 2];

    // ray quadratic coefficients
    float a  = fmaf(dx, dx, fmaf(dy, dy, dz * dz));
    float b  = 2.0f * fmaf(ox, dx, fmaf(oy, dy, oz * dz));
    float c  = fmaf(ox, ox, fmaf(oy, oy, oz * oz)) - 1.0f;        // intersect form (unchanged)
    float qc = fmaf(ox, ox, fmaf(oy, oy, fmaf(oz, oz, 1e-12f)));  // |o|^2 + eps for sdf

    // sphere intersect with bounding sphere R=1
    float under = fmaf(b, b, -4.0f * a * c);
    bool  mask = under > 0.0f;
    float sq = fsqrt_fast(fmaxf(under, 0.0f));
    float nearv = mask ? (-sq - b) * 0.5f : 0.0f;
    float farv  = mask ? ( sq - b) * 0.5f : 0.0f;
    nearv = fmaxf(nearv, 0.01f);
    farv  = fmaxf(farv, 0.01f);

    // bidirectional sphere tracing (positions eliminated; sdf via quadratic)
    bool us = mask, ue = mask;
    float accs = nearv, acce = farv;
    float ns = us ? s_quad(a, b, qc, accs) : 0.0f;
    float ne = ue ? s_quad(a, b, qc, acce) : 0.0f;

#pragma unroll
    for (int it = 0; it < ST_ITERS; ++it) {
        float cs = us ? ns : 0.0f;
        cs = (cs <= SDF_THRESH) ? 0.0f : cs;
        us = us && (cs > SDF_THRESH);
        float ce = ue ? ne : 0.0f;
        ce = (ce <= SDF_THRESH) ? 0.0f : ce;
        ue = ue && (ce > SDF_THRESH);

        accs += cs;
        acce -= ce;
        ns = us ? s_quad(a, b, qc, accs) : 0.0f;
        ne = ue ? s_quad(a, b, qc, acce) : 0.0f;

        // line search: LINE_STEP_ITERS = 1, step = 0.5
        bool nps = ns < 0.0f;
        bool npe = ne < 0.0f;
        {
            float accs2 = fmaf(-0.5f, cs, accs);
            float s2 = s_quad(a, b, qc, accs2);
            if (nps) { accs = accs2; ns = s2; }
        }
        {
            float acce2 = fmaf(0.5f, ce, acce);
            float s2 = s_quad(a, b, qc, acce2);
            if (npe) { acce = acce2; ne = s2; }
        }
        bool ok = accs < acce;
        us = us && ok;
        ue = ue && ok;
    }
    // final _upd_mask on start side
    {
        float cs = us ? ns : 0.0f;
        cs = (cs <= SDF_THRESH) ? 0.0f : cs;
        us = us && (cs > SDF_THRESH);
    }

    bool netm  = accs < acce;
    bool smask = us && valid;

    if (valid) {
        // curr_s = o + accs*d (bit-identical to last in-loop assignment)
        out[3 * i + 0] = fmaf(accs, dx, ox);
        out[3 * i + 1] = fmaf(accs, dy, oy);
        out[3 * i + 2] = fmaf(accs, dz, oz);
        out[3 * n + i] = netm ? 1.0f : 0.0f;
        out[4 * n + i] = accs;
    }

    // block-local compaction of smask rays
    if (smask) {
        int q = atomicAdd(&s_cnt, 1);
        s_rid[q] = i;
        s_lo[q]  = accs;
        s_hi[q]  = acce;
    }
    __syncthreads();

    // ================= Phase 2: scan (4 threads/ray) =================
    int cnt = s_cnt;
    int sub = tid & (LPR - 1);          // lane in quad

    for (int base = 0; base < cnt; base += BLK / LPR) {
        int rslot = base + (tid >> 2);
        bool active = rslot < cnt;
        int q = active ? rslot : 0;

        int rid = s_rid[q];
        float smin = s_lo[q];
        float smax = s_hi[q];
        float range = smax - smin;

        float rox = cam[3 * rid + 0], roy = cam[3 * rid + 1], roz = cam[3 * rid + 2];
        float rdx = dirs[3 * rid + 0], rdy = dirs[3 * rid + 1], rdz = dirs[3 * rid + 2];
        bool obj = objm[rid] != 0;

        float a2 = fmaf(rdx, rdx, fmaf(rdy, rdy, rdz * rdz));
        float b2 = 2.0f * fmaf(rox, rdx, fmaf(roy, rdy, roz * rdz));
        float c2 = fmaf(rox, rox, fmaf(roy, roy, fmaf(roz, roz, 1e-12f)));

        int   kbase = sub * KPL;
        int   ind_neg = NSTEPS, oidx = NSTEPS - 1;
        float best_q = 1e30f;
#pragma unroll 5
        for (int kk = 0; kk < KPL; ++kk) {
            int k = kbase + kk;
            float t  = (float)k * INV99;
            float z  = fmaf(t, range, smin);
            float qv = q_quad(a2, b2, c2, z);
            ind_neg  = min(ind_neg, (qv < R2THRESH) ? k : NSTEPS);
            if (qv < best_q) { best_q = qv; oidx = k; }
        }

        // quad reduction (xor 1,2 stays inside the quad)
#pragma unroll
        for (int m = 1; m < LPR; m <<= 1) {
            int   in2 = __shfl_xor_sync(FULL, ind_neg, m);
            float bq2 = __shfl_xor_sync(FULL, best_q, m);
            int   oi2 = __shfl_xor_sync(FULL, oidx, m);
            ind_neg = min(ind_neg, in2);
            if (bq2 < best_q || (bq2 == best_q && oi2 < oidx)) {
                best_q = bq2; oidx = oi2;
            }
        }

        bool net_surface = (ind_neg < NSTEPS);
        int  ind = net_surface ? ind_neg : (NSTEPS - 1);
        bool sec = net_surface && obj;   // complement of p_out over queued rays

        if (active && sub == 0) {
            out[3 * n + rid] = net_surface ? 1.0f : 0.0f;
            if (!sec) {
                float z_o = fmaf((float)oidx * INV99, range, smin);
                out[3 * rid + 0] = fmaf(z_o, rdx, rox);
                out[3 * rid + 1] = fmaf(z_o, rdy, roy);
                out[3 * rid + 2] = fmaf(z_o, rdz, roz);
                out[4 * n + rid] = z_o;
            } else {
                int   ilow  = (ind > 0) ? (ind - 1) : 0;
                float z_ind = fmaf((float)ind * INV99, range, smin);
                float z_l   = fmaf((float)ilow * INV99, range, smin);
                int q2 = atomicAdd(&s2_cnt, 1);
                s2_rid[q2] = rid;
                s2_zl[q2]  = z_l;
                s2_zh[q2]  = z_ind;
            }
        }
    }
    __syncthreads();

    // ================= Phase 3: secant (1 thread/ray) =================
    int cnt2 = s2_cnt;
    for (int q = tid; q < cnt2; q += BLK) {
        int   rid = s2_rid[q];
        float zl  = s2_zl[q];
        float zh  = s2_zh[q];

        float rox = cam[3 * rid + 0], roy = cam[3 * rid + 1], roz = cam[3 * rid + 2];
        float rdx = dirs[3 * rid + 0], rdy = dirs[3 * rid + 1], rdz = dirs[3 * rid + 2];

        float a2 = fmaf(rdx, rdx, fmaf(rdy, rdy, rdz * rdz));
        float b2 = 2.0f * fmaf(rox, rdx, fmaf(roy, rdy, roz * rdz));
        float c2 = fmaf(rox, rox, fmaf(roy, roy, fmaf(roz, roz, 1e-12f)));

        float sl = fsqrt_fast(q_quad(a2, b2, c2, zl)) - 0.5f;
        float sh = fsqrt_fast(q_quad(a2, b2, c2, zh)) - 0.5f;

        float den = sh - sl;
        den = (den == 0.0f) ? 1.0f : den;
        float z = zl - sl * __fdividef(zh - zl, den);
#pragma unroll
        for (int k = 0; k < NSECANT; ++k) {
            float s = fsqrt_fast(q_quad(a2, b2, c2, z)) - 0.5f;
            if (s > 0.0f) { zl = z; sl = s; }
            if (s < 0.0f) { zh = z; sh = s; }
            den = sh - sl;
            den = (den == 0.0f) ? 1.0f : den;
            z = zl - sl * __fdividef(zh - zl, den);
        }

        out[3 * rid + 0] = fmaf(z, rdx, rox);
        out[3 * rid + 1] = fmaf(z, rdy, roy);
        out[3 * rid + 2] = fmaf(z, rdz, roz);
        out[4 * n + rid] = z;
        // net_mask for sec rays already written in phase 2
    }
}

} // namespace rt

extern "C" void kernel_launch(void* const* d_in, const int* in_sizes, int n_in,
                              void* d_out, int out_size)
{
    const float* cam  = (const float*)d_in[0];
    const float* dirs = (const float*)d_in[1];
    const int*   objm = (const int*)d_in[2];
    float* out = (float*)d_out;

    int n = out_size / 5;
    int blocks = (n + rt::BLK - 1) / rt::BLK;
    rt::fused_kernel<<<blocks, rt::BLK>>>(cam, dirs, objm, out, n);
}

// round 13
// speedup vs baseline: 1.2937x; 1.0022x over previous
#include <cuda_runtime.h>

// RayTracing, SINGLE fused kernel, block-local compaction, QUADRATIC sdf.
//  |o+t*d|^2 = a*t^2 + b*t + |o|^2  -> each sdf eval is 2 FMA (+ sqrt if needed).
//  Phase 1: trace 128 rays/block (1 thread/ray) -> outputs + smask queue.
//           Select chains merged; ns/ne kept raw (consumers gated by us/ue) --
//           case-analysis identical to the reference's _upd_mask/where chain.
//  Phase 2: sqrt-free 100-step scan at 4 threads/ray (quad shuffle reduce,
//           exact first-occurrence tie-break; t = fk*INV99 with fk += 1.0f,
//           bit-identical to (float)k*INV99). Non-sec rays finalize with z_o;
//           sec rays push bracket to queue2.
//  Phase 3: secant at 1 thread/ray over queue2.
//
// Output layout (float32): [curr_pts (N*3)][net_mask (N)][acc_s (N)], N = out_size/5.
// object_mask arrives as int32.

namespace rt {

constexpr int   ST_ITERS   = 10;
constexpr float SDF_THRESH = 5e-5f;
constexpr int   NSTEPS     = 100;
constexpr int   NSECANT    = 8;
constexpr float INV99      = 1.0f / 99.0f;
constexpr float R2THRESH   = 0.25f;    // SDF_RADIUS^2
constexpr int   LPR        = 4;        // lanes per ray in scan
constexpr int   KPL        = 25;       // 100/4, exact
constexpr int   BLK        = 128;

__device__ __forceinline__ float fsqrt_fast(float x) {
    float y;
    asm("sqrt.approx.f32 %0, %1;" : "=f"(y) : "f"(x));
    return y;
}

// q(t) = a*t^2 + b*t + qc  (qc = |o|^2 + 1e-12)
__device__ __forceinline__ float q_quad(float qa, float qb, float qc, float t) {
    return fmaf(t, fmaf(t, qa, qb), qc);
}

// sdf along ray = sqrt(q(t)) - 0.5
__device__ __forceinline__ float s_quad(float qa, float qb, float qc, float t) {
    return fsqrt_fast(q_quad(qa, qb, qc, t)) - 0.5f;
}

__global__ void __launch_bounds__(BLK, 12)
fused_kernel(const float* __restrict__ cam,
             const float* __restrict__ dirs,
             const int* __restrict__ objm,
             float* __restrict__ out, int n)
{
    const unsigned FULL = 0xffffffffu;
    __shared__ int   s_cnt, s2_cnt;
    __shared__ int   s_rid[BLK];
    __shared__ float s_lo[BLK], s_hi[BLK];
    __shared__ int   s2_rid[BLK];
    __shared__ float s2_zl[BLK], s2_zh[BLK];

    int tid = threadIdx.x;
    if (tid == 0) { s_cnt = 0; s2_cnt = 0; }
    __syncthreads();

    // ================= Phase 1: trace =================
    int i = blockIdx.x * BLK + tid;
    bool valid = i < n;
    int j = valid ? i : 0;

    float ox = cam[3 * j + 0], oy = cam[3 * j + 1], oz = cam[3 * j + 2];
    float dx = dirs[3 * j + 0], dy = dirs[3 * j + 1], dz = dirs[3 * j + 2];

    // ray quadratic coefficients
    float a  = fmaf(dx, dx, fmaf(dy, dy, dz * dz));
    float b  = 2.0f * fmaf(ox, dx, fmaf(oy, dy, oz * dz));
    float c  = fmaf(ox, ox, fmaf(oy, oy, oz * oz)) - 1.0f;        // intersect form (unchanged)
    float qc = fmaf(ox, ox, fmaf(oy, oy, fmaf(oz, oz, 1e-12f)));  // |o|^2 + eps for sdf

    // sphere intersect with bounding sphere R=1
    float under = fmaf(b, b, -4.0f * a * c);
    bool  mask = under > 0.0f;
    float sq = fsqrt_fast(fmaxf(under, 0.0f));
    float nearv = mask ? (-sq - b) * 0.5f : 0.0f;
    float farv  = mask ? ( sq - b) * 0.5f : 0.0f;
    nearv = fmaxf(nearv, 0.01f);
    farv  = fmaxf(farv, 0.01f);

    // bidirectional sphere tracing. ns/ne held RAW (un-zeroed); every
    // consumer is gated by us/ue, equivalent to the reference's zeroing.
    bool us = mask, ue = mask;
    float accs = nearv, acce = farv;
    float ns = s_quad(a, b, qc, accs);
    float ne = s_quad(a, b, qc, acce);

#pragma unroll
    for (int it = 0; it < ST_ITERS; ++it) {
        // merged _upd_mask: usn = us && ns>TH; cs = usn ? ns : 0
        bool usn = us && (ns > SDF_THRESH);
        float cs = usn ? ns : 0.0f;
        us = usn;
        bool uen = ue && (ne > SDF_THRESH);
        float ce = uen ? ne : 0.0f;
        ue = uen;

        accs += cs;
        acce -= ce;
        ns = s_quad(a, b, qc, accs);
        ne = s_quad(a, b, qc, acce);

        // line search: LINE_STEP_ITERS = 1, step = 0.5
        bool nps = us && (ns < 0.0f);   // gate replaces reference's zeroing
        bool npe = ue && (ne < 0.0f);
        {
            float accs2 = fmaf(-0.5f, cs, accs);
            float s2 = s_quad(a, b, qc, accs2);
            if (nps) { accs = accs2; ns = s2; }
        }
        {
            float acce2 = fmaf(0.5f, ce, acce);
            float s2 = s_quad(a, b, qc, acce2);
            if (npe) { acce = acce2; ne = s2; }
        }
        bool ok = accs < acce;
        us = us && ok;
        ue = ue && ok;
    }
    // final _upd_mask on start side (gated: equivalent to zeroed-ns form)
    us = us && (ns > SDF_THRESH);

    bool netm  = accs < acce;
    bool smask = us && valid;

    if (valid) {
        // curr_s = o + accs*d (bit-identical to last in-loop assignment)
        out[3 * i + 0] = fmaf(accs, dx, ox);
        out[3 * i + 1] = fmaf(accs, dy, oy);
        out[3 * i + 2] = fmaf(accs, dz, oz);
        out[3 * n + i] = netm ? 1.0f : 0.0f;
        out[4 * n + i] = accs;
    }

    // block-local compaction of smask rays
    if (smask) {
        int q = atomicAdd(&s_cnt, 1);
        s_rid[q] = i;
        s_lo[q]  = accs;
        s_hi[q]  = acce;
    }
    __syncthreads();

    // ================= Phase 2: scan (4 threads/ray) =================
    int cnt = s_cnt;
    int sub = tid & (LPR - 1);          // lane in quad

    for (int base = 0; base < cnt; base += BLK / LPR) {
        int rslot = base + (tid >> 2);
        bool active = rslot < cnt;
        int q = active ? rslot : 0;

        int rid = s_rid[q];
        float smin = s_lo[q];
        float smax = s_hi[q];
        float range = smax - smin;

        float rox = cam[3 * rid + 0], roy = cam[3 * rid + 1], roz = cam[3 * rid + 2];
        float rdx = dirs[3 * rid + 0], rdy = dirs[3 * rid + 1], rdz = dirs[3 * rid + 2];
        bool obj = objm[rid] != 0;

        float a2 = fmaf(rdx, rdx, fmaf(rdy, rdy, rdz * rdz));
        float b2 = 2.0f * fmaf(rox, rdx, fmaf(roy, rdy, roz * rdz));
        float c2 = fmaf(rox, rox, fmaf(roy, roy, fmaf(roz, roz, 1e-12f)));

        int   kbase = sub * KPL;
        int   ind_neg = NSTEPS, oidx = NSTEPS - 1;
        float best_q = 1e30f;
        float fk = (float)kbase;         // exact; +1.0f stays exact (k < 2^24)
#pragma unroll 5
        for (int kk = 0; kk < KPL; ++kk) {
            int k = kbase + kk;
            float t  = fk * INV99;       // bit-identical to (float)k * INV99
            float z  = fmaf(t, range, smin);
            float qv = q_quad(a2, b2, c2, z);
            ind_neg  = min(ind_neg, (qv < R2THRESH) ? k : NSTEPS);
            if (qv < best_q) { best_q = qv; oidx = k; }
            fk += 1.0f;
        }

        // quad reduction (xor 1,2 stays inside the quad)
#pragma unroll
        for (int m = 1; m < LPR; m <<= 1) {
            int   in2 = __shfl_xor_sync(FULL, ind_neg, m);
            float bq2 = __shfl_xor_sync(FULL, best_q, m);
            int   oi2 = __shfl_xor_sync(FULL, oidx, m);
            ind_neg = min(ind_neg, in2);
            if (bq2 < best_q || (bq2 == best_q && oi2 < oidx)) {
                best_q = bq2; oidx = oi2;
            }
        }

        bool net_surface = (ind_neg < NSTEPS);
        int  ind = net_surface ? ind_neg : (NSTEPS - 1);
        bool sec = net_surface && obj;   // complement of p_out over queued rays

        if (active && sub == 0) {
            out[3 * n + rid] = net_surface ? 1.0f : 0.0f;
            if (!sec) {
                float z_o = fmaf((float)oidx * INV99, range, smin);
                out[3 * rid + 0] = fmaf(z_o, rdx, rox);
                out[3 * rid + 1] = fmaf(z_o, rdy, roy);
                out[3 * rid + 2] = fmaf(z_o, rdz, roz);
                out[4 * n + rid] = z_o;
            } else {
                int   ilow  = (ind > 0) ? (ind - 1) : 0;
                float z_ind = fmaf((float)ind * INV99, range, smin);
                float z_l   = fmaf((float)ilow * INV99, range, smin);
                int q2 = atomicAdd(&s2_cnt, 1);
                s2_rid[q2] = rid;
                s2_zl[q2]  = z_l;
                s2_zh[q2]  = z_ind;
            }
        }
    }
    __syncthreads();

    // ================= Phase 3: secant (1 thread/ray) =================
    int cnt2 = s2_cnt;
    for (int q = tid; q < cnt2; q += BLK) {
        int   rid = s2_rid[q];
        float zl  = s2_zl[q];
        float zh  = s2_zh[q];

        float rox = cam[3 * rid + 0], roy = cam[3 * rid + 1], roz = cam[3 * rid + 2];
        float rdx = dirs[3 * rid + 0], rdy = dirs[3 * rid + 1], rdz = dirs[3 * rid + 2];

        float a2 = fmaf(rdx, rdx, fmaf(rdy, rdy, rdz * rdz));
        float b2 = 2.0f * fmaf(rox, rdx, fmaf(roy, rdy, roz * rdz));
        float c2 = fmaf(rox, rox, fmaf(roy, roy, fmaf(roz, roz, 1e-12f)));

        float sl = fsqrt_fast(q_quad(a2, b2, c2, zl)) - 0.5f;
        float sh = fsqrt_fast(q_quad(a2, b2, c2, zh)) - 0.5f;

        float den = sh - sl;
        den = (den == 0.0f) ? 1.0f : den;
        float z = zl - sl * __fdividef(zh - zl, den);
#pragma unroll
        for (int k = 0; k < NSECANT; ++k) {
            float s = fsqrt_fast(q_quad(a2, b2, c2, z)) - 0.5f;
            if (s > 0.0f) { zl = z; sl = s; }
            if (s < 0.0f) { zh = z; sh = s; }
            den = sh - sl;
            den = (den == 0.0f) ? 1.0f : den;
            z = zl - sl * __fdividef(zh - zl, den);
        }

        out[3 * rid + 0] = fmaf(z, rdx, rox);
        out[3 * rid + 1] = fmaf(z, rdy, roy);
        out[3 * rid + 2] = fmaf(z, rdz, roz);
        out[4 * n + rid] = z;
        // net_mask for sec rays already written in phase 2
    }
}

} // namespace rt

extern "C" void kernel_launch(void* const* d_in, const int* in_sizes, int n_in,
                              void* d_out, int out_size)
{
    const float* cam  = (const float*)d_in[0];
    const float* dirs = (const float*)d_in[1];
    const int*   objm = (const int*)d_in[2];
    float* out = (float*)d_out;

    int n = out_size / 5;
    int blocks = (n + rt::BLK - 1) / rt::BLK;
    rt::fused_kernel<<<blocks, rt::BLK>>>(cam, dirs, objm, out, n);
}